// round 12
// baseline (speedup 1.0000x reference)
#include <cuda_runtime.h>
#include <cuda_fp16.h>
#include <math.h>
#include <stdint.h>

#define B_    32
#define NV    1556
#define NI    256
#define NTOK  1812      // NV + NI
#define D     512
#define IMGD  2048
#define SCALEF 0.08838834764831845f   // (512/4)^-0.5

// ======================= device scratch (no allocs allowed) =================
__device__ __align__(16) __half g_x [B_*NTOK*D];          // fp16 activations (concat)
__device__ __align__(16) __half g_im[B_*NI*IMGD];         // fp16 img features
__device__ __align__(16) __half g_o1[B_*NV*D];            // fp16 proj output
__device__ __align__(16) __half g_fw[D*IMGD];             // fp16 weights
__device__ __align__(16) __half g_qkw[2*D*D];             // [q_w;k_w]
__device__ __align__(16) __half g_pw[D*D];
__device__ __align__(16) __half g_nw[D*D];
__device__ __align__(16) float g_q[B_*NTOK*D];
__device__ __align__(16) float g_k[B_*NTOK*D];
__device__ __align__(16) float g_gvec[B_*D];
__device__            float g_alog[B_*NTOK];

// ======================= helpers ============================================
__device__ __forceinline__ uint32_t smem_u32(const void* p) {
    uint32_t a;
    asm("{ .reg .u64 t; cvta.to.shared.u64 t, %1; cvt.u32.u64 %0, t; }" : "=r"(a) : "l"(p));
    return a;
}
#define CP_ASYNC16(dst, src) \
    asm volatile("cp.async.cg.shared.global [%0], [%1], 16;" :: "r"(dst), "l"(src))
#define CP_COMMIT()  asm volatile("cp.async.commit_group;" ::: "memory")
#define CP_WAIT1()   asm volatile("cp.async.wait_group 1;" ::: "memory")
#define CP_WAIT0()   asm volatile("cp.async.wait_group 0;" ::: "memory")

__device__ __forceinline__ void ldsm_x4(uint32_t* r, uint32_t addr) {
    asm volatile("ldmatrix.sync.aligned.m8n8.x4.shared.b16 {%0,%1,%2,%3}, [%4];"
        : "=r"(r[0]), "=r"(r[1]), "=r"(r[2]), "=r"(r[3]) : "r"(addr));
}
__device__ __forceinline__ void mma_f16(float* c, const uint32_t* a, const uint32_t* b) {
    asm volatile("mma.sync.aligned.m16n8k16.row.col.f32.f16.f16.f32 "
        "{%0,%1,%2,%3}, {%4,%5,%6,%7}, {%8,%9}, {%0,%1,%2,%3};"
        : "+f"(c[0]), "+f"(c[1]), "+f"(c[2]), "+f"(c[3])
        : "r"(a[0]), "r"(a[1]), "r"(a[2]), "r"(a[3]), "r"(b[0]), "r"(b[1]));
}

// ======================= conversion kernels =================================
__global__ __launch_bounds__(256) void half_arr(const float* __restrict__ s,
                                                __half* __restrict__ d, int n4) {
    int i = blockIdx.x * blockDim.x + threadIdx.x;
    if (i >= n4) return;
    float4 v = ((const float4*)s)[i];
    __half2 a, b;
    a.x = __float2half_rn(v.x); a.y = __float2half_rn(v.y);
    b.x = __float2half_rn(v.z); b.y = __float2half_rn(v.w);
    ((__half2*)d)[i*2] = a; ((__half2*)d)[i*2+1] = b;
}
#define W4Q (D*D/4)
__global__ __launch_bounds__(256) void half_w4(const float* __restrict__ qw,
                                               const float* __restrict__ kw,
                                               const float* __restrict__ pw,
                                               const float* __restrict__ nw) {
    int i = blockIdx.x * blockDim.x + threadIdx.x;
    const float* src; __half* d; int j;
    if      (i < W4Q)   { src = qw; d = g_qkw;       j = i; }
    else if (i < 2*W4Q) { src = kw; d = g_qkw + D*D; j = i - W4Q; }
    else if (i < 3*W4Q) { src = pw; d = g_pw;        j = i - 2*W4Q; }
    else                { src = nw; d = g_nw;        j = i - 3*W4Q; }
    float4 v = ((const float4*)src)[j];
    __half2 a, b;
    a.x = __float2half_rn(v.x); a.y = __float2half_rn(v.y);
    b.x = __float2half_rn(v.z); b.y = __float2half_rn(v.w);
    ((__half2*)d)[j*2] = a; ((__half2*)d)[j*2+1] = b;
}
__global__ __launch_bounds__(256) void half_verts(const float* __restrict__ v, int n4) {
    int i = blockIdx.x * blockDim.x + threadIdx.x;
    if (i >= n4) return;
    int i4 = i * 4;
    int b = i4 / (NV * D);
    int rem = i4 - b * NV * D;
    size_t dst = (size_t)b * NTOK * D + rem;
    float4 x = *(const float4*)(v + i4);
    __half2 a, c;
    a.x = __float2half_rn(x.x); a.y = __float2half_rn(x.y);
    c.x = __float2half_rn(x.z); c.y = __float2half_rn(x.w);
    *((__half2*)(g_x + dst))     = a;
    *((__half2*)(g_x + dst + 2)) = c;
}

// ======================= mma.sync fp16 GEMM =================================
// CTA 128x256, 8 warps (2 x 4), warp tile 64x64, BK=64, double-buffered smem.
// Per k16: 8 ldsm_x4 -> 32 independent MMAs (ratio 4).
// MODE 0 FC:    A=g_im [8192,2048]      -> x fp16 (img rows of g_x)
// MODE 1 QK:    A=g_x  [57984,512], W=[q_w;k_w] N=1024 -> g_q / g_k fp32
// MODE 3 PROJ:  A=(gvec ⊙ k) on the fly -> g_o1 fp16  (epi += q)
// MODE 4 FINAL: A=g_o1 [49792,512]      -> d_out fp32 (epi += verts)
#define ROWB   144            // 64 fp16 (128B) + 16B pad
#define TILEA  (128*ROWB)     // 18432 B
#define TILEW  (256*ROWB)     // 36864 B
#define BUFB   (TILEA+TILEW)  // 55296 B
#define SM_SZ  (1024 + 2*BUFB) // 111616 B

template<int MODE>
__global__ __launch_bounds__(256)
void mma_gemm(const float* __restrict__ bias,
              const float* __restrict__ extra,   // k_b for QK, verts for FINAL
              float* __restrict__ outf)          // d_out for FINAL
{
    constexpr int K  = (MODE == 0) ? IMGD : D;
    constexpr int KT = K / 64;

    extern __shared__ __align__(128) char smem[];
    float* sbias = (float*)smem;
    char*  sdata = smem + 1024;
    const uint32_t s_data = smem_u32(smem) + 1024;

    const int tid = threadIdx.x, wid = tid >> 5, lane = tid & 31;
    const int wm = wid & 1, wn = wid >> 1;
    const int m0 = blockIdx.y * 128, n0 = blockIdx.x * 256;

    {   // bias: 256 entries
        int idx = n0 + tid;
        if (MODE == 1) sbias[tid] = (idx < 512) ? bias[idx] : extra[idx - 512];
        else           sbias[tid] = bias[idx];
    }

    const __half* A = (MODE == 0) ? g_im : (MODE == 4) ? g_o1 : g_x;
    const __half* W = (MODE == 0) ? g_fw : (MODE == 1) ? g_qkw :
                      (MODE == 3) ? g_pw : g_nw;

    auto issue = [&](int c, int buf) {
        const int k0 = c * 64;
        const uint32_t dbase = s_data + buf * BUFB;
        if (MODE != 3) {
            #pragma unroll
            for (int i = 0; i < 4; i++) {        // A: 1024 granules of 16B
                int g = tid + i * 256;
                int row = g >> 3, seg = g & 7;
                uint32_t dst = dbase + row * ROWB + seg * 16;
                const char* sa = (const char*)(A + (size_t)(m0 + row) * K + k0) + seg * 16;
                CP_ASYNC16(dst, sa);
            }
        } else {
            #pragma unroll
            for (int i = 0; i < 8; i++) {        // 2048 granules of 4 floats
                int g = tid + i * 256;
                int row = g >> 4, c4 = (g & 15) * 4;
                int r = m0 + row, b = r / NV, n = r - b * NV;
                float4 kv = *(const float4*)(g_k + ((size_t)b * NTOK + n) * D + k0 + c4);
                float4 gv = *(const float4*)(g_gvec + b * D + k0 + c4);
                union { __half h[4]; unsigned long long u; } uu;
                uu.h[0] = __float2half_rn(kv.x * gv.x);
                uu.h[1] = __float2half_rn(kv.y * gv.y);
                uu.h[2] = __float2half_rn(kv.z * gv.z);
                uu.h[3] = __float2half_rn(kv.w * gv.w);
                *(unsigned long long*)(sdata + buf * BUFB + row * ROWB + c4 * 2) = uu.u;
            }
        }
        #pragma unroll
        for (int i = 0; i < 8; i++) {            // W: 2048 granules of 16B
            int g = tid + i * 256;
            int row = g >> 3, seg = g & 7;
            uint32_t dst = dbase + TILEA + row * ROWB + seg * 16;
            const char* sw = (const char*)(W + (size_t)(n0 + row) * K + k0) + seg * 16;
            CP_ASYNC16(dst, sw);
        }
        CP_COMMIT();
    };

    float acc[4][8][4];
    #pragma unroll
    for (int a = 0; a < 4; a++)
        #pragma unroll
        for (int b = 0; b < 8; b++)
            #pragma unroll
            for (int c = 0; c < 4; c++) acc[a][b][c] = 0.f;

    issue(0, 0);
    for (int c = 0; c < KT; c++) {
        const int cur = c & 1;
        if (c + 1 < KT) { issue(c + 1, cur ^ 1); CP_WAIT1(); }
        else            { CP_WAIT0(); }
        __syncthreads();

        const uint32_t bA = s_data + cur * BUFB;
        #pragma unroll
        for (int k16 = 0; k16 < 4; k16++) {
            uint32_t ah[4][4], w4[4][4];
            #pragma unroll
            for (int mt = 0; mt < 4; mt++) {
                uint32_t addr = bA + (uint32_t)((wm * 64 + mt * 16 + (lane & 15)) * ROWB)
                              + k16 * 32 + (lane >> 4) * 16;
                ldsm_x4(ah[mt], addr);
            }
            #pragma unroll
            for (int np = 0; np < 4; np++) {
                uint32_t addr = bA + TILEA
                              + (uint32_t)((wn * 64 + np * 16 + (lane & 15)) * ROWB)
                              + k16 * 32 + (lane >> 4) * 16;
                ldsm_x4(w4[np], addr);
            }
            #pragma unroll
            for (int mt = 0; mt < 4; mt++)
                #pragma unroll
                for (int np = 0; np < 4; np++) {
                    uint32_t b0[2] = { w4[np][0], w4[np][2] };   // n-tile 2*np
                    uint32_t b1[2] = { w4[np][1], w4[np][3] };   // n-tile 2*np+1
                    mma_f16(acc[mt][2*np],   ah[mt], b0);
                    mma_f16(acc[mt][2*np+1], ah[mt], b1);
                }
        }
        __syncthreads();
    }

    // ---------------- epilogue ----------------
    float* qkbase = nullptr; int coff0 = 0;
    if (MODE == 1) { qkbase = (n0 < 512) ? g_q : g_k; coff0 = n0 & 511; }

    #pragma unroll
    for (int mt = 0; mt < 4; mt++) {
        #pragma unroll
        for (int nt = 0; nt < 8; nt++) {
            const int cl  = wn * 64 + nt * 8 + (lane & 3) * 2;
            const int col = n0 + cl;
            const float b0 = sbias[cl], b1 = sbias[cl + 1];
            #pragma unroll
            for (int h = 0; h < 2; h++) {
                const int row = m0 + wm * 64 + mt * 16 + (lane >> 2) + h * 8;
                float v0 = acc[mt][nt][h * 2 + 0] + b0;
                float v1 = acc[mt][nt][h * 2 + 1] + b1;

                if (MODE == 1) {
                    float2* p = (float2*)(qkbase + (size_t)row * D + coff0 + cl);
                    float2 v; v.x = v0; v.y = v1; *p = v;
                } else if (MODE == 4) {
                    const float2 e = *(const float2*)(extra + (size_t)row * D + col);
                    float2* p = (float2*)(outf + (size_t)row * D + col);
                    float2 v; v.x = v0 + e.x; v.y = v1 + e.y; *p = v;
                } else if (MODE == 0) {
                    int b = row >> 8, n = row & 255;
                    size_t dr = ((size_t)b * NTOK + NV + n) * D + col;
                    __half2 p;
                    p.x = __float2half_rn(v0); p.y = __float2half_rn(v1);
                    *(__half2*)(g_x + dr) = p;
                } else { // MODE 3
                    int b = row / NV, n = row - b * NV;
                    const float2 qv = *(const float2*)(g_q + ((size_t)b * NTOK + n) * D + col);
                    __half2 p;
                    p.x = __float2half_rn(v0 + qv.x); p.y = __float2half_rn(v1 + qv.y);
                    *(__half2*)(g_o1 + (size_t)row * D + col) = p;
                }
            }
        }
    }
}

// ======================= norm / softmax / gacc ==============================
__device__ __forceinline__ float blk_sum128(float v, volatile float* s) {
    #pragma unroll
    for (int o = 16; o > 0; o >>= 1) v += __shfl_xor_sync(0xffffffffu, v, o);
    if ((threadIdx.x & 31) == 0) s[threadIdx.x >> 5] = v;
    __syncthreads();
    float r = s[0] + s[1] + s[2] + s[3];
    __syncthreads();
    return r;
}
__global__ __launch_bounds__(128)
void norm_qk_kernel(const float* __restrict__ wg) {
    __shared__ float s[4];
    const int row = blockIdx.x, t = threadIdx.x;
    float4* qp = (float4*)(g_q + (size_t)row * D);
    float4* kp = (float4*)(g_k + (size_t)row * D);
    float4 q4 = qp[t], k4 = kp[t];
    float sq = q4.x*q4.x + q4.y*q4.y + q4.z*q4.z + q4.w*q4.w;
    float sk = k4.x*k4.x + k4.y*k4.y + k4.z*k4.z + k4.w*k4.w;
    float tq = blk_sum128(sq, s);
    float tk = blk_sum128(sk, s);
    float qs = 1.f / fmaxf(sqrtf(tq), 1e-12f);
    float ks = 1.f / fmaxf(sqrtf(tk), 1e-12f);
    q4.x*=qs; q4.y*=qs; q4.z*=qs; q4.w*=qs;
    k4.x*=ks; k4.y*=ks; k4.z*=ks; k4.w*=ks;
    qp[t] = q4; kp[t] = k4;
    float4 w4 = ((const float4*)wg)[t];
    float dp = q4.x*w4.x + q4.y*w4.y + q4.z*w4.z + q4.w*w4.w;
    float tot = blk_sum128(dp, s);
    if (t == 0) g_alog[row] = tot * SCALEF;
}
__global__ __launch_bounds__(256)
void softmax_kernel() {
    __shared__ float s[8];
    const int b = blockIdx.x, t = threadIdx.x;
    float* L = g_alog + b * NTOK;
    float m = -1e30f;
    for (int i = t; i < NTOK; i += 256) m = fmaxf(m, L[i]);
    #pragma unroll
    for (int o = 16; o > 0; o >>= 1) m = fmaxf(m, __shfl_xor_sync(0xffffffffu, m, o));
    if ((t & 31) == 0) s[t >> 5] = m;
    __syncthreads();
    float M = s[0];
    #pragma unroll
    for (int w = 1; w < 8; w++) M = fmaxf(M, s[w]);
    __syncthreads();
    float sum = 0.f;
    for (int i = t; i < NTOK; i += 256) sum += expf(L[i] - M);
    #pragma unroll
    for (int o = 16; o > 0; o >>= 1) sum += __shfl_xor_sync(0xffffffffu, sum, o);
    if ((t & 31) == 0) s[t >> 5] = sum;
    __syncthreads();
    float S = s[0]+s[1]+s[2]+s[3]+s[4]+s[5]+s[6]+s[7];
    float inv = 1.f / S;
    for (int i = t; i < NTOK; i += 256) L[i] = expf(L[i] - M) * inv;
    for (int i = t; i < D;    i += 256) g_gvec[b * D + i] = 0.f;
}
__global__ __launch_bounds__(512)
void gacc_kernel() {
    const int b = blockIdx.y, c = blockIdx.x, t = threadIdx.x;
    const int n0 = c * 151;
    const float* qb = g_q + ((size_t)b * NTOK + n0) * D + t;
    const float* wp = g_alog + b * NTOK + n0;
    float acc = 0.f;
    #pragma unroll 4
    for (int i = 0; i < 151; i++)
        acc = fmaf(wp[i], qb[(size_t)i * D], acc);
    atomicAdd(&g_gvec[b * D + t], acc);
}

// ======================= launch =============================================
extern "C" void kernel_launch(void* const* d_in, const int* in_sizes, int n_in,
                              void* d_out, int out_size)
{
    const float* verts   = (const float*)d_in[0];
    const float* imgf    = (const float*)d_in[1];
    const float* fc_w    = (const float*)d_in[2];
    const float* fc_b    = (const float*)d_in[3];
    const float* q_w     = (const float*)d_in[4];
    const float* q_b     = (const float*)d_in[5];
    const float* k_w     = (const float*)d_in[6];
    const float* k_b     = (const float*)d_in[7];
    const float* w_g     = (const float*)d_in[8];
    const float* proj_w  = (const float*)d_in[9];
    const float* proj_b  = (const float*)d_in[10];
    const float* final_w = (const float*)d_in[11];
    const float* final_b = (const float*)d_in[12];
    float* out = (float*)d_out;

    cudaFuncSetAttribute(mma_gemm<0>, cudaFuncAttributeMaxDynamicSharedMemorySize, SM_SZ);
    cudaFuncSetAttribute(mma_gemm<1>, cudaFuncAttributeMaxDynamicSharedMemorySize, SM_SZ);
    cudaFuncSetAttribute(mma_gemm<3>, cudaFuncAttributeMaxDynamicSharedMemorySize, SM_SZ);
    cudaFuncSetAttribute(mma_gemm<4>, cudaFuncAttributeMaxDynamicSharedMemorySize, SM_SZ);

    __half *fw, *im;
    cudaGetSymbolAddress((void**)&fw, g_fw);
    cudaGetSymbolAddress((void**)&im, g_im);

    // ordering: GEMMs land at launch indices 3 and 5 (ncu -s target either way)
    half_arr<<<(D*IMGD/4 + 255)/256, 256>>>(fc_w, fw, D*IMGD/4);               // L0
    half_arr<<<(B_*NI*IMGD/4 + 255)/256, 256>>>(imgf, im, B_*NI*IMGD/4);       // L1
    half_w4<<<(4*W4Q + 255)/256, 256>>>(q_w, k_w, proj_w, final_w);            // L2
    mma_gemm<0><<<dim3(2,  64), 256, SM_SZ>>>(fc_b, nullptr, nullptr);         // L3 fc
    half_verts<<<(B_*NV*D/4 + 255)/256, 256>>>(verts, B_*NV*D/4);              // L4
    mma_gemm<1><<<dim3(4, 453), 256, SM_SZ>>>(q_b,  k_b,     nullptr);         // L5 q+k
    norm_qk_kernel<<<B_ * NTOK, 128>>>(w_g);
    softmax_kernel<<<B_, 256>>>();
    gacc_kernel<<<dim3(12, B_), 512>>>();
    mma_gemm<3><<<dim3(2, 389), 256, SM_SZ>>>(proj_b,  nullptr, nullptr);      // proj (+q)
    mma_gemm<4><<<dim3(2, 389), 256, SM_SZ>>>(final_b, verts,   out);          // final (+verts)
}

// round 13
// speedup vs baseline: 1.2327x; 1.2327x over previous
#include <cuda_runtime.h>
#include <cuda_fp16.h>
#include <math.h>
#include <stdint.h>

#define B_    32
#define NV    1556
#define NI    256
#define NTOK  1812      // NV + NI
#define D     512
#define IMGD  2048
#define SCALEF 0.08838834764831845f   // (512/4)^-0.5

// ======================= device scratch (no allocs allowed) =================
__device__ __align__(16) __half g_x  [B_*NTOK*D];         // fp16 activations (concat)
__device__ __align__(16) __half g_im [B_*NI*IMGD];        // fp16 img features
__device__ __align__(16) __half g_o1 [B_*NV*D];           // fp16 proj output
__device__ __align__(16) __half g_q16[B_*NTOK*D];         // fp16 q (normalized)
__device__ __align__(16) __half g_k16[B_*NTOK*D];         // fp16 k (normalized)
__device__ __align__(16) __half g_fw[D*IMGD];
__device__ __align__(16) __half g_qkw[2*D*D];             // [q_w;k_w]
__device__ __align__(16) __half g_pw[D*D];
__device__ __align__(16) __half g_nw[D*D];
__device__ __align__(16) float g_gvec[B_*D];
__device__            float g_alog[B_*NTOK];

// ======================= helpers ============================================
__device__ __forceinline__ uint32_t smem_u32(const void* p) {
    uint32_t a;
    asm("{ .reg .u64 t; cvta.to.shared.u64 t, %1; cvt.u32.u64 %0, t; }" : "=r"(a) : "l"(p));
    return a;
}
#define CP_ASYNC16(dst, src) \
    asm volatile("cp.async.cg.shared.global [%0], [%1], 16;" :: "r"(dst), "l"(src))
#define CP_COMMIT()  asm volatile("cp.async.commit_group;" ::: "memory")
#define CP_WAIT1()   asm volatile("cp.async.wait_group 1;" ::: "memory")
#define CP_WAIT0()   asm volatile("cp.async.wait_group 0;" ::: "memory")

__device__ __forceinline__ void ldsm_x4(uint32_t* r, uint32_t addr) {
    asm volatile("ldmatrix.sync.aligned.m8n8.x4.shared.b16 {%0,%1,%2,%3}, [%4];"
        : "=r"(r[0]), "=r"(r[1]), "=r"(r[2]), "=r"(r[3]) : "r"(addr));
}
__device__ __forceinline__ void ldsm_x2(uint32_t* r, uint32_t addr) {
    asm volatile("ldmatrix.sync.aligned.m8n8.x2.shared.b16 {%0,%1}, [%2];"
        : "=r"(r[0]), "=r"(r[1]) : "r"(addr));
}
__device__ __forceinline__ void mma_f16(float* c, const uint32_t* a, const uint32_t* b) {
    asm volatile("mma.sync.aligned.m16n8k16.row.col.f32.f16.f16.f32 "
        "{%0,%1,%2,%3}, {%4,%5,%6,%7}, {%8,%9}, {%0,%1,%2,%3};"
        : "+f"(c[0]), "+f"(c[1]), "+f"(c[2]), "+f"(c[3])
        : "r"(a[0]), "r"(a[1]), "r"(a[2]), "r"(a[3]), "r"(b[0]), "r"(b[1]));
}

// ======================= conversion kernels =================================
__global__ __launch_bounds__(256) void half_arr(const float* __restrict__ s,
                                                __half* __restrict__ d, int n4) {
    int i = blockIdx.x * blockDim.x + threadIdx.x;
    if (i >= n4) return;
    float4 v = ((const float4*)s)[i];
    __half2 a, b;
    a.x = __float2half_rn(v.x); a.y = __float2half_rn(v.y);
    b.x = __float2half_rn(v.z); b.y = __float2half_rn(v.w);
    ((__half2*)d)[i*2] = a; ((__half2*)d)[i*2+1] = b;
}
#define W4Q (D*D/4)
__global__ __launch_bounds__(256) void half_w4(const float* __restrict__ qw,
                                               const float* __restrict__ kw,
                                               const float* __restrict__ pw,
                                               const float* __restrict__ nw) {
    int i = blockIdx.x * blockDim.x + threadIdx.x;
    const float* src; __half* d; int j;
    if      (i < W4Q)   { src = qw; d = g_qkw;       j = i; }
    else if (i < 2*W4Q) { src = kw; d = g_qkw + D*D; j = i - W4Q; }
    else if (i < 3*W4Q) { src = pw; d = g_pw;        j = i - 2*W4Q; }
    else                { src = nw; d = g_nw;        j = i - 3*W4Q; }
    float4 v = ((const float4*)src)[j];
    __half2 a, b;
    a.x = __float2half_rn(v.x); a.y = __float2half_rn(v.y);
    b.x = __float2half_rn(v.z); b.y = __float2half_rn(v.w);
    ((__half2*)d)[j*2] = a; ((__half2*)d)[j*2+1] = b;
}
__global__ __launch_bounds__(256) void half_verts(const float* __restrict__ v, int n4) {
    int i = blockIdx.x * blockDim.x + threadIdx.x;
    if (i >= n4) return;
    int i4 = i * 4;
    int b = i4 / (NV * D);
    int rem = i4 - b * NV * D;
    size_t dst = (size_t)b * NTOK * D + rem;
    float4 x = *(const float4*)(v + i4);
    __half2 a, c;
    a.x = __float2half_rn(x.x); a.y = __float2half_rn(x.y);
    c.x = __float2half_rn(x.z); c.y = __float2half_rn(x.w);
    *((__half2*)(g_x + dst))     = a;
    *((__half2*)(g_x + dst + 2)) = c;
}

// ======================= mma.sync fp16 GEMM =================================
// CTA 128x128, 8 warps (2 x 4), warp tile 64x32, BK=64.
// 3-stage cp.async pipeline, ONE __syncthreads per k-tile, 2 CTAs/SM.
// MODE 0 FC:    A=g_im [8192,2048]      -> x fp16 (img rows of g_x)
// MODE 1 QK:    A=g_x  [57984,512], W=[q_w;k_w] N=1024 -> g_q16 / g_k16 fp16
// MODE 3 PROJ:  A=(gvec ⊙ k16) on the fly -> g_o1 fp16  (epi += q16)
// MODE 4 FINAL: A=g_o1 [49792,512]      -> d_out fp32 (epi += verts)
#define ROWB  144             // 64 fp16 (128B) + 16B pad
#define TILEB (128*ROWB)      // 18432 B
#define BUFB  (2*TILEB)       // A, W = 36864 B
#define NBUF  3
#define SM_SZ (512 + NBUF*BUFB)  // 111104 B -> 2 CTAs/SM

template<int MODE>
__global__ __launch_bounds__(256)
void mma_gemm(const float* __restrict__ bias,
              const float* __restrict__ extra,   // k_b for QK, verts for FINAL
              float* __restrict__ outf)          // d_out for FINAL
{
    constexpr int K  = (MODE == 0) ? IMGD : D;
    constexpr int KT = K / 64;

    extern __shared__ __align__(128) char smem[];
    float* sbias = (float*)smem;
    char*  sdata = smem + 512;
    const uint32_t s_data = smem_u32(smem) + 512;

    const int tid = threadIdx.x, wid = tid >> 5, lane = tid & 31;
    const int wm = wid & 1, wn = wid >> 1;
    const int m0 = blockIdx.y * 128, n0 = blockIdx.x * 128;

    if (tid < 128) {
        if (MODE == 1) sbias[tid] = (n0 < 512) ? bias[n0 + tid] : extra[n0 - 512 + tid];
        else           sbias[tid] = bias[n0 + tid];
    }

    const __half* A = (MODE == 0) ? g_im : (MODE == 4) ? g_o1 : g_x;
    const __half* W = (MODE == 0) ? g_fw : (MODE == 1) ? g_qkw :
                      (MODE == 3) ? g_pw : g_nw;

    auto issue = [&](int c) {
        const int k0  = c * 64;
        const int buf = c % NBUF;
        const uint32_t dbase = s_data + buf * BUFB;
        if (MODE != 3) {
            #pragma unroll
            for (int i = 0; i < 4; i++) {        // A: 1024 granules of 16B
                int g = tid + i * 256;
                int row = g >> 3, seg = g & 7;
                uint32_t dst = dbase + row * ROWB + seg * 16;
                const char* sa = (const char*)(A + (size_t)(m0 + row) * K + k0) + seg * 16;
                CP_ASYNC16(dst, sa);
            }
        } else {
            #pragma unroll
            for (int i = 0; i < 4; i++) {        // 1024 granules of 8 halves
                int g = tid + i * 256;
                int row = g >> 3, c8 = (g & 7) * 8;
                int r = m0 + row, b = r / NV, n = r - b * NV;
                const __half* kp = g_k16 + ((size_t)b * NTOK + n) * D + k0 + c8;
                const float*  gp = g_gvec + b * D + k0 + c8;
                uint4 kv = *(const uint4*)kp;
                const __half2* kh = (const __half2*)&kv;
                union { __half h[8]; uint4 u; } uu;
                #pragma unroll
                for (int j = 0; j < 4; j++) {
                    float2 kf = __half22float2(kh[j]);
                    uu.h[j*2]   = __float2half_rn(kf.x * gp[j*2]);
                    uu.h[j*2+1] = __float2half_rn(kf.y * gp[j*2+1]);
                }
                *(uint4*)(sdata + buf * BUFB + row * ROWB + c8 * 2) = uu.u;
            }
        }
        #pragma unroll
        for (int i = 0; i < 4; i++) {            // W: 1024 granules of 16B
            int g = tid + i * 256;
            int row = g >> 3, seg = g & 7;
            uint32_t dst = dbase + TILEB + row * ROWB + seg * 16;
            const char* sw = (const char*)(W + (size_t)(n0 + row) * K + k0) + seg * 16;
            CP_ASYNC16(dst, sw);
        }
        CP_COMMIT();
    };

    float acc[4][4][4];
    #pragma unroll
    for (int a = 0; a < 4; a++)
        #pragma unroll
        for (int b = 0; b < 4; b++)
            #pragma unroll
            for (int c = 0; c < 4; c++) acc[a][b][c] = 0.f;

    issue(0);
    issue(1);
    for (int c = 0; c < KT; c++) {
        if (c + 1 < KT) CP_WAIT1(); else CP_WAIT0();   // tile c resident
        __syncthreads();                               // all warps past tile c-1
        if (c + 2 < KT) issue(c + 2);                  // refill buf (c+2)%3

        const uint32_t bA = s_data + (c % NBUF) * BUFB;
        #pragma unroll
        for (int k16 = 0; k16 < 4; k16++) {
            uint32_t ah[4][4], wf[4][2];
            #pragma unroll
            for (int nt = 0; nt < 4; nt++) {
                uint32_t addr = bA + TILEB
                              + (uint32_t)((wn * 32 + nt * 8 + (lane & 7)) * ROWB)
                              + k16 * 32 + ((lane >> 3) & 1) * 16;
                ldsm_x2(wf[nt], addr);
            }
            #pragma unroll
            for (int mt = 0; mt < 4; mt++) {
                uint32_t addr = bA + (uint32_t)((wm * 64 + mt * 16 + (lane & 15)) * ROWB)
                              + k16 * 32 + (lane >> 4) * 16;
                ldsm_x4(ah[mt], addr);
            }
            #pragma unroll
            for (int mt = 0; mt < 4; mt++)
                #pragma unroll
                for (int nt = 0; nt < 4; nt++)
                    mma_f16(acc[mt][nt], ah[mt], wf[nt]);
        }
    }

    // ---------------- epilogue ----------------
    __half* qkbase = nullptr; int coff0 = 0;
    if (MODE == 1) { qkbase = (n0 < 512) ? g_q16 : g_k16; coff0 = n0 & 511; }

    #pragma unroll
    for (int mt = 0; mt < 4; mt++) {
        #pragma unroll
        for (int nt = 0; nt < 4; nt++) {
            const int cl  = wn * 32 + nt * 8 + (lane & 3) * 2;
            const int col = n0 + cl;
            const float b0 = sbias[cl], b1 = sbias[cl + 1];
            #pragma unroll
            for (int h = 0; h < 2; h++) {
                const int row = m0 + wm * 64 + mt * 16 + (lane >> 2) + h * 8;
                float v0 = acc[mt][nt][h * 2 + 0] + b0;
                float v1 = acc[mt][nt][h * 2 + 1] + b1;

                if (MODE == 1) {
                    __half2 p;
                    p.x = __float2half_rn(v0); p.y = __float2half_rn(v1);
                    *(__half2*)(qkbase + (size_t)row * D + coff0 + cl) = p;
                } else if (MODE == 4) {
                    const float2 e = *(const float2*)(extra + (size_t)row * D + col);
                    float2* p = (float2*)(outf + (size_t)row * D + col);
                    float2 v; v.x = v0 + e.x; v.y = v1 + e.y; *p = v;
                } else if (MODE == 0) {
                    int b = row >> 8, n = row & 255;
                    size_t dr = ((size_t)b * NTOK + NV + n) * D + col;
                    __half2 p;
                    p.x = __float2half_rn(v0); p.y = __float2half_rn(v1);
                    *(__half2*)(g_x + dr) = p;
                } else { // MODE 3
                    int b = row / NV, n = row - b * NV;
                    const __half2 qv = *(const __half2*)(g_q16 + ((size_t)b * NTOK + n) * D + col);
                    float2 qf = __half22float2(qv);
                    __half2 p;
                    p.x = __float2half_rn(v0 + qf.x); p.y = __float2half_rn(v1 + qf.y);
                    *(__half2*)(g_o1 + (size_t)row * D + col) = p;
                }
            }
        }
    }
}

// ======================= norm / softmax / gacc ==============================
__device__ __forceinline__ float blk_sum128(float v, volatile float* s) {
    #pragma unroll
    for (int o = 16; o > 0; o >>= 1) v += __shfl_xor_sync(0xffffffffu, v, o);
    if ((threadIdx.x & 31) == 0) s[threadIdx.x >> 5] = v;
    __syncthreads();
    float r = s[0] + s[1] + s[2] + s[3];
    __syncthreads();
    return r;
}
__global__ __launch_bounds__(128)
void norm_qk_kernel(const float* __restrict__ wg) {
    __shared__ float s[4];
    const int row = blockIdx.x, t = threadIdx.x;    // 128 threads, 4 halves each
    __half2* qp = (__half2*)(g_q16 + (size_t)row * D) + t * 2;
    __half2* kp = (__half2*)(g_k16 + (size_t)row * D) + t * 2;
    float2 q0 = __half22float2(qp[0]), q1 = __half22float2(qp[1]);
    float2 k0 = __half22float2(kp[0]), k1 = __half22float2(kp[1]);
    float sq = q0.x*q0.x + q0.y*q0.y + q1.x*q1.x + q1.y*q1.y;
    float sk = k0.x*k0.x + k0.y*k0.y + k1.x*k1.x + k1.y*k1.y;
    float tq = blk_sum128(sq, s);
    float tk = blk_sum128(sk, s);
    float qs = 1.f / fmaxf(sqrtf(tq), 1e-12f);
    float ks = 1.f / fmaxf(sqrtf(tk), 1e-12f);
    q0.x*=qs; q0.y*=qs; q1.x*=qs; q1.y*=qs;
    k0.x*=ks; k0.y*=ks; k1.x*=ks; k1.y*=ks;
    __half2 w;
    w.x=__float2half_rn(q0.x); w.y=__float2half_rn(q0.y); qp[0]=w;
    w.x=__float2half_rn(q1.x); w.y=__float2half_rn(q1.y); qp[1]=w;
    w.x=__float2half_rn(k0.x); w.y=__float2half_rn(k0.y); kp[0]=w;
    w.x=__float2half_rn(k1.x); w.y=__float2half_rn(k1.y); kp[1]=w;
    float4 w4 = ((const float4*)wg)[t];
    float dp = q0.x*w4.x + q0.y*w4.y + q1.x*w4.z + q1.y*w4.w;
    float tot = blk_sum128(dp, s);
    if (t == 0) g_alog[row] = tot * SCALEF;
}
__global__ __launch_bounds__(256)
void softmax_kernel() {
    __shared__ float s[8];
    const int b = blockIdx.x, t = threadIdx.x;
    float* L = g_alog + b * NTOK;
    float m = -1e30f;
    for (int i = t; i < NTOK; i += 256) m = fmaxf(m, L[i]);
    #pragma unroll
    for (int o = 16; o > 0; o >>= 1) m = fmaxf(m, __shfl_xor_sync(0xffffffffu, m, o));
    if ((t & 31) == 0) s[t >> 5] = m;
    __syncthreads();
    float M = s[0];
    #pragma unroll
    for (int w = 1; w < 8; w++) M = fmaxf(M, s[w]);
    __syncthreads();
    float sum = 0.f;
    for (int i = t; i < NTOK; i += 256) sum += expf(L[i] - M);
    #pragma unroll
    for (int o = 16; o > 0; o >>= 1) sum += __shfl_xor_sync(0xffffffffu, sum, o);
    if ((t & 31) == 0) s[t >> 5] = sum;
    __syncthreads();
    float S = s[0]+s[1]+s[2]+s[3]+s[4]+s[5]+s[6]+s[7];
    float inv = 1.f / S;
    for (int i = t; i < NTOK; i += 256) L[i] = expf(L[i] - M) * inv;
    for (int i = t; i < D;    i += 256) g_gvec[b * D + i] = 0.f;
}
__global__ __launch_bounds__(512)
void gacc_kernel() {
    const int b = blockIdx.y, c = blockIdx.x, t = threadIdx.x;
    const int n0 = c * 151;
    const __half* qb = g_q16 + ((size_t)b * NTOK + n0) * D + t;
    const float* wp = g_alog + b * NTOK + n0;
    float acc = 0.f;
    #pragma unroll 4
    for (int i = 0; i < 151; i++)
        acc = fmaf(wp[i], __half2float(qb[(size_t)i * D]), acc);
    atomicAdd(&g_gvec[b * D + t], acc);
}

// ======================= launch =============================================
extern "C" void kernel_launch(void* const* d_in, const int* in_sizes, int n_in,
                              void* d_out, int out_size)
{
    const float* verts   = (const float*)d_in[0];
    const float* imgf    = (const float*)d_in[1];
    const float* fc_w    = (const float*)d_in[2];
    const float* fc_b    = (const float*)d_in[3];
    const float* q_w     = (const float*)d_in[4];
    const float* q_b     = (const float*)d_in[5];
    const float* k_w     = (const float*)d_in[6];
    const float* k_b     = (const float*)d_in[7];
    const float* w_g     = (const float*)d_in[8];
    const float* proj_w  = (const float*)d_in[9];
    const float* proj_b  = (const float*)d_in[10];
    const float* final_w = (const float*)d_in[11];
    const float* final_b = (const float*)d_in[12];
    float* out = (float*)d_out;

    cudaFuncSetAttribute(mma_gemm<0>, cudaFuncAttributeMaxDynamicSharedMemorySize, SM_SZ);
    cudaFuncSetAttribute(mma_gemm<1>, cudaFuncAttributeMaxDynamicSharedMemorySize, SM_SZ);
    cudaFuncSetAttribute(mma_gemm<3>, cudaFuncAttributeMaxDynamicSharedMemorySize, SM_SZ);
    cudaFuncSetAttribute(mma_gemm<4>, cudaFuncAttributeMaxDynamicSharedMemorySize, SM_SZ);

    __half *fw, *im;
    cudaGetSymbolAddress((void**)&fw, g_fw);
    cudaGetSymbolAddress((void**)&im, g_im);

    // ordering: GEMMs land at launch indices 3 and 5 (ncu -s 5 profiles QK or fc)
    half_arr<<<(D*IMGD/4 + 255)/256, 256>>>(fc_w, fw, D*IMGD/4);               // L0
    half_arr<<<(B_*NI*IMGD/4 + 255)/256, 256>>>(imgf, im, B_*NI*IMGD/4);       // L1
    half_w4<<<(4*W4Q + 255)/256, 256>>>(q_w, k_w, proj_w, final_w);            // L2
    mma_gemm<0><<<dim3(4,  64), 256, SM_SZ>>>(fc_b, nullptr, nullptr);         // L3 fc
    half_verts<<<(B_*NV*D/4 + 255)/256, 256>>>(verts, B_*NV*D/4);              // L4
    mma_gemm<1><<<dim3(8, 453), 256, SM_SZ>>>(q_b,  k_b,     nullptr);         // L5 q+k
    norm_qk_kernel<<<B_ * NTOK, 128>>>(w_g);
    softmax_kernel<<<B_, 256>>>();
    gacc_kernel<<<dim3(12, B_), 512>>>();
    mma_gemm<3><<<dim3(4, 389), 256, SM_SZ>>>(proj_b,  nullptr, nullptr);      // proj (+q)
    mma_gemm<4><<<dim3(4, 389), 256, SM_SZ>>>(final_b, verts,   out);          // final (+verts)
}